// round 16
// baseline (speedup 1.0000x reference)
#include <cuda_runtime.h>
#include <cuda_bf16.h>
#include <cstdint>

#define Bn 16384
#define Kn 2048
#define Dn 128
#define D4 (Dn/4)      // 32
#define MTILE 128
#define NCHUNK 128
#define NCHUNKS (Kn/NCHUNK)   // 16
#define THREADS 512

#define INF_F (__int_as_float(0x7f800000))

// ---------------------------------------------------------------------------
// Device scratch (no allocations allowed)
// ---------------------------------------------------------------------------
__device__ float g_c2[Kn];
__device__ int   g_label[Bn];
__device__ int   g_k2[Bn];
__device__ int   g_nflag;
__device__ int   g_flags[Bn];
__device__ __nv_bfloat16 g_xhi[Bn * Dn];
__device__ __nv_bfloat16 g_xlo[Bn * Dn];
__device__ __nv_bfloat16 g_chi[Kn * Dn];
__device__ __nv_bfloat16 g_clo[Kn * Dn];

// ---------------------------------------------------------------------------
// Baseline-PTX helpers (sm_80+; no sm_103a-only features)
// ---------------------------------------------------------------------------
__device__ __forceinline__ uint32_t smem_to_u32(const void* p) {
    uint32_t a;
    asm("{ .reg .u64 t; cvta.to.shared.u64 t, %1; cvt.u32.u64 %0, t; }"
        : "=r"(a) : "l"(p));
    return a;
}

__device__ __forceinline__ void ldsm4(uint32_t* r, uint32_t addr) {
    asm volatile("ldmatrix.sync.aligned.m8n8.x4.shared.b16 {%0,%1,%2,%3}, [%4];"
                 : "=r"(r[0]), "=r"(r[1]), "=r"(r[2]), "=r"(r[3]) : "r"(addr));
}

__device__ __forceinline__ void mma16816(float* d, const uint32_t* a, const uint32_t* b) {
    asm volatile(
        "mma.sync.aligned.m16n8k16.row.col.f32.bf16.bf16.f32 "
        "{%0,%1,%2,%3}, {%4,%5,%6,%7}, {%8,%9}, {%0,%1,%2,%3};"
        : "+f"(d[0]), "+f"(d[1]), "+f"(d[2]), "+f"(d[3])
        : "r"(a[0]), "r"(a[1]), "r"(a[2]), "r"(a[3]), "r"(b[0]), "r"(b[1]));
}

#define CP_ASYNC16(dst, src) \
    asm volatile("cp.async.cg.shared.global [%0], [%1], 16;" \
                 :: "r"(dst), "l"(src) : "memory")
#define CP_COMMIT() asm volatile("cp.async.commit_group;" ::: "memory")
#define CP_WAIT(n)  asm volatile("cp.async.wait_group %0;" :: "n"(n) : "memory")

// ---------------------------------------------------------------------------
// SMEM layout: row stride 272B (256B data + 16B pad, ldmatrix conflict-free)
// ---------------------------------------------------------------------------
#define ROWB 272
#define TILEB (128 * ROWB)            // 34816
#define OFF_AHI 0
#define OFF_ALO TILEB
#define OFF_B   (2*TILEB)             // 69632
#define BSTAGE  (2*TILEB)             // per-stage size (hi+lo)
#define OFF_C2  (OFF_B + 2*BSTAGE)    // 208896
#define OFF_RED OFF_B                 // merge scratch aliases B (after last chunk)
#define SMEM_TOTAL (OFF_C2 + 8192)    // 217088

// ---------------------------------------------------------------------------
// Fused conversion: x hi/lo split, then c hi/lo + c2 (ranking). The c range
// starts at a warp-aligned offset so warp-collective reductions are intact.
// ---------------------------------------------------------------------------
#define NX4 (Bn * D4)    // 524288 float4's of x
#define NC4 (Kn * D4)    // 65536 float4's of c
__global__ void convert_all_kernel(const float* __restrict__ x,
                                   const float* __restrict__ c) {
    int i = blockIdx.x * blockDim.x + threadIdx.x;
    if (i == 0) g_nflag = 0;
    if (i < NX4) {
        float4 q = ((const float4*)x)[i];
        __nv_bfloat16 h[4], l[4];
        float f[4] = {q.x, q.y, q.z, q.w};
#pragma unroll
        for (int j = 0; j < 4; j++) {
            h[j] = __float2bfloat16_rn(f[j]);
            l[j] = __float2bfloat16_rn(__fsub_rn(f[j], __bfloat162float(h[j])));
        }
        *reinterpret_cast<uint2*>(g_xhi + 4 * (size_t)i) = *reinterpret_cast<uint2*>(h);
        *reinterpret_cast<uint2*>(g_xlo + 4 * (size_t)i) = *reinterpret_cast<uint2*>(l);
    } else if (i < NX4 + NC4) {
        int j4 = i - NX4;
        float4 q = ((const float4*)c)[j4];
        __nv_bfloat16 h[4], l[4];
        float f[4] = {q.x, q.y, q.z, q.w};
        float s = 0.f;
#pragma unroll
        for (int j = 0; j < 4; j++) {
            h[j] = __float2bfloat16_rn(f[j]);
            l[j] = __float2bfloat16_rn(__fsub_rn(f[j], __bfloat162float(h[j])));
            s = __fadd_rn(s, __fmul_rn(f[j], f[j]));
        }
        *reinterpret_cast<uint2*>(g_chi + 4 * (size_t)j4) = *reinterpret_cast<uint2*>(h);
        *reinterpret_cast<uint2*>(g_clo + 4 * (size_t)j4) = *reinterpret_cast<uint2*>(l);
        // warp covers exactly one c row (ranking-only; order-insensitive)
#pragma unroll
        for (int off = 16; off >= 1; off >>= 1)
            s = __fadd_rn(s, __shfl_down_sync(0xffffffffu, s, off));
        if ((threadIdx.x & 31) == 0) g_c2[j4 >> 5] = s;
    }
}

// ---------------------------------------------------------------------------
// Pass 1: HMMA bf16x3 GEMM (dot = hh + hl + lh) + top-2 by r = c2 - 2*dot.
// 128 blocks x 512 threads. Warp grid 4(M) x 4(N); warp tile 32x32.
// B double-buffered via cp.async. MMA issue is PASS-MAJOR (RAW distance 8).
// [Chunk loop byte-identical to R15 (113.6us / rel_err 0.0); only the final
//  merge block changes: compacted flag emission, no g_r1/g_r2 stores.]
// ---------------------------------------------------------------------------
__global__ __launch_bounds__(THREADS, 1)
void hmma_argmin_kernel() {
    extern __shared__ char smem[];
    const uint32_t sb = smem_to_u32(smem);
    const int tid = threadIdx.x;
    const int wid = tid >> 5;
    const int lane = tid & 31;
    const int warpM = wid & 3;
    const int warpN = wid >> 2;      // 0..3
    const int R0 = blockIdx.x * MTILE;

    float* c2s = (float*)(smem + OFF_C2);

    // Prologue cp.async group 0: A tiles (hi,lo) + B chunk 0 (hi,lo)
#pragma unroll
    for (int t = 0; t < 4; t++) {
        int idx = tid + t * THREADS;     // 0..2047
        int row = idx >> 4;
        int u = idx & 15;
        uint32_t so = (uint32_t)(row * ROWB + u * 16);
        size_t go = (size_t)(R0 + row) * Dn + u * 8;
        CP_ASYNC16(sb + OFF_AHI + so, (const char*)(g_xhi + go));
        CP_ASYNC16(sb + OFF_ALO + so, (const char*)(g_xlo + go));
        size_t gb = (size_t)row * Dn + u * 8;    // chunk 0
        CP_ASYNC16(sb + OFF_B + so, (const char*)(g_chi + gb));
        CP_ASYNC16(sb + OFF_B + TILEB + so, (const char*)(g_clo + gb));
    }
    CP_COMMIT();
    for (int i = tid; i < Kn; i += THREADS) c2s[i] = g_c2[i];

    const int li = lane >> 3;
    const int lr = lane & 7;
    const uint32_t a_off = (uint32_t)(warpM * 32 + (li & 1) * 8 + lr) * ROWB
                         + (uint32_t)(li >> 1) * 16;
    const uint32_t b_off = (uint32_t)(warpN * 32 + (li >> 1) * 8 + lr) * ROWB
                         + (uint32_t)(li & 1) * 16;

    // persistent top-2 state: slot s = mt*2 + mhalf
    float rt1[4], rt2[4];
    int kt1[4], kt2[4];
#pragma unroll
    for (int s = 0; s < 4; s++) { rt1[s] = INF_F; rt2[s] = INF_F; kt1[s] = 0; kt2[s] = 0; }

    const int t4 = lane & 3;

    for (int ch = 0; ch < NCHUNKS; ch++) {
        const int kc = ch * NCHUNK;
        const uint32_t bcur = OFF_B + (uint32_t)(ch & 1) * BSTAGE;

        // Issue next chunk's B into the other stage (overlaps with this MMA)
        if (ch + 1 < NCHUNKS) {
            const uint32_t bnxt = OFF_B + (uint32_t)((ch + 1) & 1) * BSTAGE;
            const int kn = (ch + 1) * NCHUNK;
#pragma unroll
            for (int t = 0; t < 4; t++) {
                int idx = tid + t * THREADS;
                int row = idx >> 4;
                int u = idx & 15;
                uint32_t so = (uint32_t)(row * ROWB + u * 16);
                size_t gb = (size_t)(kn + row) * Dn + u * 8;
                CP_ASYNC16(sb + bnxt + so, (const char*)(g_chi + gb));
                CP_ASYNC16(sb + bnxt + TILEB + so, (const char*)(g_clo + gb));
            }
            CP_COMMIT();
            CP_WAIT(1);      // current stage (older group) complete
        } else {
            CP_WAIT(0);
        }
        __syncthreads();

        float acc[2][4][4];
#pragma unroll
        for (int mt = 0; mt < 2; mt++)
#pragma unroll
            for (int nt = 0; nt < 4; nt++)
#pragma unroll
                for (int c = 0; c < 4; c++) acc[mt][nt][c] = 0.f;

#pragma unroll
        for (int kt = 0; kt < 8; kt++) {
            const uint32_t kb = kt * 32;
            uint32_t ah[2][4], al[2][4], bh[2][4], bl[2][4];
#pragma unroll
            for (int mt = 0; mt < 2; mt++) {
                ldsm4(ah[mt], sb + OFF_AHI + a_off + mt * (16 * ROWB) + kb);
                ldsm4(al[mt], sb + OFF_ALO + a_off + mt * (16 * ROWB) + kb);
            }
#pragma unroll
            for (int np = 0; np < 2; np++) {
                ldsm4(bh[np], sb + bcur + b_off + np * (16 * ROWB) + kb);
                ldsm4(bl[np], sb + bcur + TILEB + b_off + np * (16 * ROWB) + kb);
            }
            // PASS-MAJOR: 8 independent accumulators between reuses of any acc
#pragma unroll
            for (int mt = 0; mt < 2; mt++)       // hh
#pragma unroll
                for (int np = 0; np < 2; np++) {
                    mma16816(acc[mt][np * 2 + 0], ah[mt], &bh[np][0]);
                    mma16816(acc[mt][np * 2 + 1], ah[mt], &bh[np][2]);
                }
#pragma unroll
            for (int mt = 0; mt < 2; mt++)       // hl
#pragma unroll
                for (int np = 0; np < 2; np++) {
                    mma16816(acc[mt][np * 2 + 0], ah[mt], &bl[np][0]);
                    mma16816(acc[mt][np * 2 + 1], ah[mt], &bl[np][2]);
                }
#pragma unroll
            for (int mt = 0; mt < 2; mt++)       // lh
#pragma unroll
                for (int np = 0; np < 2; np++) {
                    mma16816(acc[mt][np * 2 + 0], al[mt], &bh[np][0]);
                    mma16816(acc[mt][np * 2 + 1], al[mt], &bh[np][2]);
                }
        }

        // Epilogue: r = c2 - 2*dot, update per-row top-2. k ascending per slot.
        const int kbase = kc + warpN * 32;
#pragma unroll
        for (int nt = 0; nt < 4; nt++) {
            int k0 = kbase + nt * 8 + 2 * t4;
            float c2a = c2s[k0];
            float c2b = c2s[k0 + 1];
#pragma unroll
            for (int mt = 0; mt < 2; mt++) {
#pragma unroll
                for (int half = 0; half < 2; half++) {
                    int s = mt * 2 + half;
                    float ra = __fmaf_rn(-2.0f, acc[mt][nt][half * 2 + 0], c2a);
                    if (ra < rt1[s]) { rt2[s] = rt1[s]; kt2[s] = kt1[s]; rt1[s] = ra; kt1[s] = k0; }
                    else if (ra < rt2[s]) { rt2[s] = ra; kt2[s] = k0; }
                    float rb = __fmaf_rn(-2.0f, acc[mt][nt][half * 2 + 1], c2b);
                    if (rb < rt1[s]) { rt2[s] = rt1[s]; kt2[s] = kt1[s]; rt1[s] = rb; kt1[s] = k0 + 1; }
                    else if (rb < rt2[s]) { rt2[s] = rb; kt2[s] = k0 + 1; }
                }
            }
        }
        __syncthreads();   // all reads of current stage done before it is overwritten
    }

    // Cross-source merge: row m has 16 sources (warpN x t4). Scratch aliases B.
    float* pr1 = (float*)(smem + OFF_RED);
    int*   pk1 = (int*)(smem + OFF_RED + 8192);
    float* pr2 = (float*)(smem + OFF_RED + 16384);
    int*   pk2 = (int*)(smem + OFF_RED + 24576);
    const int src = warpN * 4 + t4;
#pragma unroll
    for (int s = 0; s < 4; s++) {
        int m = warpM * 32 + (s >> 1) * 16 + (lane >> 2) + (s & 1) * 8;
        pr1[m * 16 + src] = rt1[s]; pk1[m * 16 + src] = kt1[s];
        pr2[m * 16 + src] = rt2[s]; pk2[m * 16 + src] = kt2[s];
    }
    __syncthreads();
    if (tid < MTILE) {
        int m = tid;
        float g1 = INF_F, g2 = INF_F;
        int gk1 = 0, gk2 = 0;
#pragma unroll
        for (int h = 0; h < 16; h++) {
            float a1 = pr1[m * 16 + h]; int a1k = pk1[m * 16 + h];
            float a2 = pr2[m * 16 + h]; int a2k = pk2[m * 16 + h];
            if (a1 < g1 || (a1 == g1 && a1k < gk1)) {
                g2 = g1; gk2 = gk1; g1 = a1; gk1 = a1k;
            } else if (a1 < g2 || (a1 == g2 && a1k < gk2)) {
                g2 = a1; gk2 = a1k;
            }
            if (a2 < g1 || (a2 == g1 && a2k < gk1)) {
                g2 = g1; gk2 = gk1; g1 = a2; gk1 = a2k;
            } else if (a2 < g2 || (a2 == g2 && a2k < gk2)) {
                g2 = a2; gk2 = a2k;
            }
        }
        g_label[R0 + m] = gk1;
        g_k2[R0 + m] = gk2;
        if (__fsub_rn(g2, g1) < 1e-4f) {     // compacted flag for exact redo
            int idx = atomicAdd(&g_nflag, 1);
            g_flags[idx] = R0 + m;
        }
    }
}

// ---------------------------------------------------------------------------
// Pass 2: exact fixup over the COMPACTED ambiguous list (warp per row).
// Body is the bit-verified reference replica (rel_err=0.0 in R6/R10/R15):
//   x2/c2: XLA warp row-reduce; dot: sequential FFMA chain, k ascending;
//   fl(fl(x2+c2) - fl(2*dot)), clamp, fp32 sqrt, tie -> lowest k.
// ---------------------------------------------------------------------------
__global__ void fixup_kernel(const float* __restrict__ x, const float* __restrict__ c) {
    const int gwarp = (blockIdx.x * blockDim.x + threadIdx.x) >> 5;
    const int nwarps = (gridDim.x * blockDim.x) >> 5;
    const int lane = threadIdx.x & 31;
    const int nflag = g_nflag;

    for (int fi = gwarp; fi < nflag; fi += nwarps) {
        int row = g_flags[fi];
        int ka = g_label[row];
        int kb = g_k2[row];
        const float* xr = x + (size_t)row * Dn;

        float a = 0.f;
#pragma unroll
        for (int i = 0; i < 4; i++) {
            float v = xr[lane + 32 * i];
            a = __fadd_rn(a, __fmul_rn(v, v));
        }
#pragma unroll
        for (int off = 16; off >= 1; off >>= 1)
            a = __fadd_rn(a, __shfl_down_sync(0xffffffffu, a, off));
        float x2 = __shfl_sync(0xffffffffu, a, 0);

        float c2ab[2];
#pragma unroll
        for (int s = 0; s < 2; s++) {
            const float* cr = c + (size_t)(s ? kb : ka) * Dn;
            float b = 0.f;
#pragma unroll
            for (int i = 0; i < 4; i++) {
                float v = cr[lane + 32 * i];
                b = __fadd_rn(b, __fmul_rn(v, v));
            }
#pragma unroll
            for (int off = 16; off >= 1; off >>= 1)
                b = __fadd_rn(b, __shfl_down_sync(0xffffffffu, b, off));
            c2ab[s] = __shfl_sync(0xffffffffu, b, 0);
        }

        float dd = 0.f;
        if (lane < 2) {
            const float* cr = c + (size_t)(lane ? kb : ka) * Dn;
            for (int d = 0; d < Dn; d++)
                dd = __fmaf_rn(xr[d], cr[d], dd);
        }
        float dota = __shfl_sync(0xffffffffu, dd, 0);
        float dotb = __shfl_sync(0xffffffffu, dd, 1);

        if (lane == 0) {
            float ta = __fsub_rn(__fadd_rn(x2, c2ab[0]), __fmul_rn(2.0f, dota));
            float tb = __fsub_rn(__fadd_rn(x2, c2ab[1]), __fmul_rn(2.0f, dotb));
            float sa = __fsqrt_rn(fmaxf(ta, 0.0f));
            float sb = __fsqrt_rn(fmaxf(tb, 0.0f));
            int win = ka;
            if (sb < sa || (sb == sa && kb < ka)) win = kb;
            g_label[row] = win;
        }
    }
}

// ---------------------------------------------------------------------------
// Fused output: gather + center passthrough + labels (validated R12-R15)
// ---------------------------------------------------------------------------
#define N1 (Bn * D4)
#define N2 (Kn * D4)
#define N3 (Bn / 4)
__global__ void out_all_kernel(const float* __restrict__ c, float* __restrict__ out) {
    int idx = blockIdx.x * blockDim.x + threadIdx.x;
    if (idx < N1) {
        int b = idx >> 5, d4 = idx & 31;
        ((float4*)out)[idx] = ((const float4*)c)[g_label[b] * D4 + d4];
    } else if (idx < N1 + N2) {
        ((float4*)out)[idx] = ((const float4*)c)[idx - N1];
    } else if (idx < N1 + N2 + N3) {
        int i = idx - N1 - N2;
        float4 v = make_float4((float)g_label[4 * i],     (float)g_label[4 * i + 1],
                               (float)g_label[4 * i + 2], (float)g_label[4 * i + 3]);
        ((float4*)out)[idx] = v;
    }
}

__global__ void gather_kernel(const float* __restrict__ c, float* __restrict__ out) {
    int idx = blockIdx.x * blockDim.x + threadIdx.x;
    if (idx >= N1) return;
    int b = idx >> 5, d4 = idx & 31;
    ((float4*)out)[idx] = ((const float4*)c)[g_label[b] * D4 + d4];
}

__global__ void label_out_kernel(float* __restrict__ dst) {
    int b = blockIdx.x * blockDim.x + threadIdx.x;
    if (b >= Bn) return;
    dst[b] = (float)g_label[b];
}

// ---------------------------------------------------------------------------
extern "C" void kernel_launch(void* const* d_in, const int* in_sizes, int n_in,
                              void* d_out, int out_size) {
    const float* x = (const float*)d_in[0];
    const float* c = (const float*)d_in[1];
    if (n_in >= 2 && in_sizes[0] == Kn * Dn && in_sizes[1] == Bn * Dn) {
        const float* t = x; x = c; c = t;
    }
    float* out = (float*)d_out;

    static bool attr_done = false;
    if (!attr_done) {
        cudaFuncSetAttribute(hmma_argmin_kernel,
                             cudaFuncAttributeMaxDynamicSharedMemorySize, SMEM_TOTAL);
        attr_done = true;
    }

    convert_all_kernel<<<(NX4 + NC4 + 255) / 256, 256>>>(x, c);
    hmma_argmin_kernel<<<Bn / MTILE, THREADS, SMEM_TOTAL>>>();
    fixup_kernel<<<64, 256>>>(x, c);

    if (out_size >= N1 * 4 + N2 * 4 + Bn) {
        out_all_kernel<<<(N1 + N2 + N3 + 255) / 256, 256>>>(c, out);
    } else if (out_size >= Bn * Dn) {
        gather_kernel<<<(N1 + 255) / 256, 256>>>(c, out);
        if (out_size - Bn * Dn >= Bn)
            label_out_kernel<<<(Bn + 255) / 256, 256>>>(out + (size_t)Bn * Dn);
    } else if (out_size >= Bn) {
        label_out_kernel<<<(Bn + 255) / 256, 256>>>(out);
    }
}

// round 17
// speedup vs baseline: 1.5497x; 1.5497x over previous
#include <cuda_runtime.h>
#include <cuda_bf16.h>
#include <cstdint>

#define Bn 16384
#define Kn 2048
#define Dn 128
#define D4 (Dn/4)      // 32
#define MTILE 128
#define NCHUNK 128
#define NCHUNKS (Kn/NCHUNK)   // 16
#define THREADS 512

#define INF_F (__int_as_float(0x7f800000))

// ---------------------------------------------------------------------------
// Device scratch (no allocations allowed)
// ---------------------------------------------------------------------------
__device__ float g_c2[Kn];
__device__ int   g_label[Bn];
__device__ float g_r1[Bn];
__device__ float g_r2[Bn];
__device__ int   g_k2[Bn];
__device__ __nv_bfloat16 g_xhi[Bn * Dn];
__device__ __nv_bfloat16 g_xlo[Bn * Dn];
__device__ __nv_bfloat16 g_chi[Kn * Dn];
__device__ __nv_bfloat16 g_clo[Kn * Dn];

// ---------------------------------------------------------------------------
// Baseline-PTX helpers (sm_80+; no sm_103a-only features)
// ---------------------------------------------------------------------------
__device__ __forceinline__ uint32_t smem_to_u32(const void* p) {
    uint32_t a;
    asm("{ .reg .u64 t; cvta.to.shared.u64 t, %1; cvt.u32.u64 %0, t; }"
        : "=r"(a) : "l"(p));
    return a;
}

__device__ __forceinline__ void ldsm4(uint32_t* r, uint32_t addr) {
    asm volatile("ldmatrix.sync.aligned.m8n8.x4.shared.b16 {%0,%1,%2,%3}, [%4];"
                 : "=r"(r[0]), "=r"(r[1]), "=r"(r[2]), "=r"(r[3]) : "r"(addr));
}

__device__ __forceinline__ void mma16816(float* d, const uint32_t* a, const uint32_t* b) {
    asm volatile(
        "mma.sync.aligned.m16n8k16.row.col.f32.bf16.bf16.f32 "
        "{%0,%1,%2,%3}, {%4,%5,%6,%7}, {%8,%9}, {%0,%1,%2,%3};"
        : "+f"(d[0]), "+f"(d[1]), "+f"(d[2]), "+f"(d[3])
        : "r"(a[0]), "r"(a[1]), "r"(a[2]), "r"(a[3]), "r"(b[0]), "r"(b[1]));
}

#define CP_ASYNC16(dst, src) \
    asm volatile("cp.async.cg.shared.global [%0], [%1], 16;" \
                 :: "r"(dst), "l"(src) : "memory")
#define CP_COMMIT() asm volatile("cp.async.commit_group;" ::: "memory")
#define CP_WAIT(n)  asm volatile("cp.async.wait_group %0;" :: "n"(n) : "memory")

// ---------------------------------------------------------------------------
// SMEM layout: row stride 272B (256B data + 16B pad, ldmatrix conflict-free)
//   A tiles (hi,lo)           :      0 ..  69632
//   B stages 0,1 (hi,lo each) :  69632 .. 208896   (aliased by merge scratch)
//   c2                        : 208896 .. 217088
// ---------------------------------------------------------------------------
#define ROWB 272
#define TILEB (128 * ROWB)            // 34816
#define OFF_AHI 0
#define OFF_ALO TILEB
#define OFF_B   (2*TILEB)             // 69632
#define BSTAGE  (2*TILEB)             // per-stage size (hi+lo)
#define OFF_C2  (OFF_B + 2*BSTAGE)    // 208896
#define OFF_RED OFF_B                 // merge scratch aliases B (after last chunk)
#define SMEM_TOTAL (OFF_C2 + 8192)    // 217088

// ---------------------------------------------------------------------------
// bf16 hi/lo split conversion for x (4 floats per thread)
// ---------------------------------------------------------------------------
__global__ void convert_kernel(const float* __restrict__ v,
                               __nv_bfloat16* __restrict__ hi,
                               __nv_bfloat16* __restrict__ lo, int n4) {
    int i = blockIdx.x * blockDim.x + threadIdx.x;
    if (i >= n4) return;
    float4 q = ((const float4*)v)[i];
    __nv_bfloat16 h[4], l[4];
    float f[4] = {q.x, q.y, q.z, q.w};
#pragma unroll
    for (int j = 0; j < 4; j++) {
        h[j] = __float2bfloat16_rn(f[j]);
        l[j] = __float2bfloat16_rn(__fsub_rn(f[j], __bfloat162float(h[j])));
    }
    *reinterpret_cast<uint2*>(hi + 4 * (size_t)i) = *reinterpret_cast<uint2*>(h);
    *reinterpret_cast<uint2*>(lo + 4 * (size_t)i) = *reinterpret_cast<uint2*>(l);
}

// convert + c2 row-norm fused for centers: warp == one row (D4 == 32)
__global__ void convert_c_kernel(const float* __restrict__ v,
                                 __nv_bfloat16* __restrict__ hi,
                                 __nv_bfloat16* __restrict__ lo) {
    int i = blockIdx.x * blockDim.x + threadIdx.x;   // float4 index
    if (i >= Kn * D4) return;
    float4 q = ((const float4*)v)[i];
    __nv_bfloat16 h[4], l[4];
    float f[4] = {q.x, q.y, q.z, q.w};
    float s = 0.f;
#pragma unroll
    for (int j = 0; j < 4; j++) {
        h[j] = __float2bfloat16_rn(f[j]);
        l[j] = __float2bfloat16_rn(__fsub_rn(f[j], __bfloat162float(h[j])));
        s = __fadd_rn(s, __fmul_rn(f[j], f[j]));
    }
    *reinterpret_cast<uint2*>(hi + 4 * (size_t)i) = *reinterpret_cast<uint2*>(h);
    *reinterpret_cast<uint2*>(lo + 4 * (size_t)i) = *reinterpret_cast<uint2*>(l);
    // warp-reduce s: warp covers exactly one row (ranking-only; order-insensitive)
#pragma unroll
    for (int off = 16; off >= 1; off >>= 1)
        s = __fadd_rn(s, __shfl_down_sync(0xffffffffu, s, off));
    if ((threadIdx.x & 31) == 0) g_c2[i >> 5] = s;
}

// ---------------------------------------------------------------------------
// Pass 1: HMMA bf16x3 GEMM (dot = hh + hl + lh) + top-2 by r = c2 - 2*dot.
// 128 blocks x 512 threads. Warp grid 4(M) x 4(N); warp tile 32x32.
// B double-buffered via cp.async. MMA issue is PASS-MAJOR (RAW distance 8).
// [Byte-identical to the kernel that measured 114.7 (R10) / 113.6 (R15)]
// ---------------------------------------------------------------------------
__global__ __launch_bounds__(THREADS, 1)
void hmma_argmin_kernel() {
    extern __shared__ char smem[];
    const uint32_t sb = smem_to_u32(smem);
    const int tid = threadIdx.x;
    const int wid = tid >> 5;
    const int lane = tid & 31;
    const int warpM = wid & 3;
    const int warpN = wid >> 2;      // 0..3
    const int R0 = blockIdx.x * MTILE;

    float* c2s = (float*)(smem + OFF_C2);

    // Prologue cp.async group 0: A tiles (hi,lo) + B chunk 0 (hi,lo)
#pragma unroll
    for (int t = 0; t < 4; t++) {
        int idx = tid + t * THREADS;     // 0..2047
        int row = idx >> 4;
        int u = idx & 15;
        uint32_t so = (uint32_t)(row * ROWB + u * 16);
        size_t go = (size_t)(R0 + row) * Dn + u * 8;
        CP_ASYNC16(sb + OFF_AHI + so, (const char*)(g_xhi + go));
        CP_ASYNC16(sb + OFF_ALO + so, (const char*)(g_xlo + go));
        size_t gb = (size_t)row * Dn + u * 8;    // chunk 0
        CP_ASYNC16(sb + OFF_B + so, (const char*)(g_chi + gb));
        CP_ASYNC16(sb + OFF_B + TILEB + so, (const char*)(g_clo + gb));
    }
    CP_COMMIT();
    for (int i = tid; i < Kn; i += THREADS) c2s[i] = g_c2[i];

    const int li = lane >> 3;
    const int lr = lane & 7;
    const uint32_t a_off = (uint32_t)(warpM * 32 + (li & 1) * 8 + lr) * ROWB
                         + (uint32_t)(li >> 1) * 16;
    const uint32_t b_off = (uint32_t)(warpN * 32 + (li >> 1) * 8 + lr) * ROWB
                         + (uint32_t)(li & 1) * 16;

    // persistent top-2 state: slot s = mt*2 + mhalf
    float rt1[4], rt2[4];
    int kt1[4], kt2[4];
#pragma unroll
    for (int s = 0; s < 4; s++) { rt1[s] = INF_F; rt2[s] = INF_F; kt1[s] = 0; kt2[s] = 0; }

    const int t4 = lane & 3;

    for (int ch = 0; ch < NCHUNKS; ch++) {
        const int kc = ch * NCHUNK;
        const uint32_t bcur = OFF_B + (uint32_t)(ch & 1) * BSTAGE;

        // Issue next chunk's B into the other stage (overlaps with this MMA)
        if (ch + 1 < NCHUNKS) {
            const uint32_t bnxt = OFF_B + (uint32_t)((ch + 1) & 1) * BSTAGE;
            const int kn = (ch + 1) * NCHUNK;
#pragma unroll
            for (int t = 0; t < 4; t++) {
                int idx = tid + t * THREADS;
                int row = idx >> 4;
                int u = idx & 15;
                uint32_t so = (uint32_t)(row * ROWB + u * 16);
                size_t gb = (size_t)(kn + row) * Dn + u * 8;
                CP_ASYNC16(sb + bnxt + so, (const char*)(g_chi + gb));
                CP_ASYNC16(sb + bnxt + TILEB + so, (const char*)(g_clo + gb));
            }
            CP_COMMIT();
            CP_WAIT(1);      // current stage (older group) complete
        } else {
            CP_WAIT(0);
        }
        __syncthreads();

        float acc[2][4][4];
#pragma unroll
        for (int mt = 0; mt < 2; mt++)
#pragma unroll
            for (int nt = 0; nt < 4; nt++)
#pragma unroll
                for (int c = 0; c < 4; c++) acc[mt][nt][c] = 0.f;

#pragma unroll
        for (int kt = 0; kt < 8; kt++) {
            const uint32_t kb = kt * 32;
            uint32_t ah[2][4], al[2][4], bh[2][4], bl[2][4];
#pragma unroll
            for (int mt = 0; mt < 2; mt++) {
                ldsm4(ah[mt], sb + OFF_AHI + a_off + mt * (16 * ROWB) + kb);
                ldsm4(al[mt], sb + OFF_ALO + a_off + mt * (16 * ROWB) + kb);
            }
#pragma unroll
            for (int np = 0; np < 2; np++) {
                ldsm4(bh[np], sb + bcur + b_off + np * (16 * ROWB) + kb);
                ldsm4(bl[np], sb + bcur + TILEB + b_off + np * (16 * ROWB) + kb);
            }
            // PASS-MAJOR: 8 independent accumulators between reuses of any acc
#pragma unroll
            for (int mt = 0; mt < 2; mt++)       // hh
#pragma unroll
                for (int np = 0; np < 2; np++) {
                    mma16816(acc[mt][np * 2 + 0], ah[mt], &bh[np][0]);
                    mma16816(acc[mt][np * 2 + 1], ah[mt], &bh[np][2]);
                }
#pragma unroll
            for (int mt = 0; mt < 2; mt++)       // hl
#pragma unroll
                for (int np = 0; np < 2; np++) {
                    mma16816(acc[mt][np * 2 + 0], ah[mt], &bl[np][0]);
                    mma16816(acc[mt][np * 2 + 1], ah[mt], &bl[np][2]);
                }
#pragma unroll
            for (int mt = 0; mt < 2; mt++)       // lh
#pragma unroll
                for (int np = 0; np < 2; np++) {
                    mma16816(acc[mt][np * 2 + 0], al[mt], &bh[np][0]);
                    mma16816(acc[mt][np * 2 + 1], al[mt], &bh[np][2]);
                }
        }

        // Epilogue: r = c2 - 2*dot, update per-row top-2. k ascending per slot.
        const int kbase = kc + warpN * 32;
#pragma unroll
        for (int nt = 0; nt < 4; nt++) {
            int k0 = kbase + nt * 8 + 2 * t4;
            float c2a = c2s[k0];
            float c2b = c2s[k0 + 1];
#pragma unroll
            for (int mt = 0; mt < 2; mt++) {
#pragma unroll
                for (int half = 0; half < 2; half++) {
                    int s = mt * 2 + half;
                    float ra = __fmaf_rn(-2.0f, acc[mt][nt][half * 2 + 0], c2a);
                    if (ra < rt1[s]) { rt2[s] = rt1[s]; kt2[s] = kt1[s]; rt1[s] = ra; kt1[s] = k0; }
                    else if (ra < rt2[s]) { rt2[s] = ra; kt2[s] = k0; }
                    float rb = __fmaf_rn(-2.0f, acc[mt][nt][half * 2 + 1], c2b);
                    if (rb < rt1[s]) { rt2[s] = rt1[s]; kt2[s] = kt1[s]; rt1[s] = rb; kt1[s] = k0 + 1; }
                    else if (rb < rt2[s]) { rt2[s] = rb; kt2[s] = k0 + 1; }
                }
            }
        }
        __syncthreads();   // all reads of current stage done before it is overwritten
    }

    // Cross-source merge: row m has 16 sources (warpN x t4). Scratch aliases B.
    float* pr1 = (float*)(smem + OFF_RED);
    int*   pk1 = (int*)(smem + OFF_RED + 8192);
    float* pr2 = (float*)(smem + OFF_RED + 16384);
    int*   pk2 = (int*)(smem + OFF_RED + 24576);
    const int src = warpN * 4 + t4;
#pragma unroll
    for (int s = 0; s < 4; s++) {
        int m = warpM * 32 + (s >> 1) * 16 + (lane >> 2) + (s & 1) * 8;
        pr1[m * 16 + src] = rt1[s]; pk1[m * 16 + src] = kt1[s];
        pr2[m * 16 + src] = rt2[s]; pk2[m * 16 + src] = kt2[s];
    }
    __syncthreads();
    if (tid < MTILE) {
        int m = tid;
        float g1 = INF_F, g2 = INF_F;
        int gk1 = 0, gk2 = 0;
#pragma unroll
        for (int h = 0; h < 16; h++) {
            float a1 = pr1[m * 16 + h]; int a1k = pk1[m * 16 + h];
            float a2 = pr2[m * 16 + h]; int a2k = pk2[m * 16 + h];
            if (a1 < g1 || (a1 == g1 && a1k < gk1)) {
                g2 = g1; gk2 = gk1; g1 = a1; gk1 = a1k;
            } else if (a1 < g2 || (a1 == g2 && a1k < gk2)) {
                g2 = a1; gk2 = a1k;
            }
            if (a2 < g1 || (a2 == g1 && a2k < gk1)) {
                g2 = g1; gk2 = gk1; g1 = a2; gk1 = a2k;
            } else if (a2 < g2 || (a2 == g2 && a2k < gk2)) {
                g2 = a2; gk2 = a2k;
            }
        }
        g_label[R0 + m] = gk1;
        g_r1[R0 + m] = g1;
        g_r2[R0 + m] = g2;
        g_k2[R0 + m] = gk2;
    }
}

// ---------------------------------------------------------------------------
// Pass 2: exact fixup for ambiguous rows (top-2 r-gap < 1e-4).
// Bit-faithful replica of the reference pipeline (verified rel_err=0.0).
// ---------------------------------------------------------------------------
__global__ void fixup_kernel(const float* __restrict__ x, const float* __restrict__ c) {
    int row = (blockIdx.x * blockDim.x + threadIdx.x) >> 5;
    int lane = threadIdx.x & 31;
    if (row >= Bn) return;
    float gap = __fsub_rn(g_r2[row], g_r1[row]);
    if (!(gap < 1e-4f)) return;

    int ka = g_label[row];
    int kb = g_k2[row];
    const float* xr = x + (size_t)row * Dn;

    float a = 0.f;
#pragma unroll
    for (int i = 0; i < 4; i++) {
        float v = xr[lane + 32 * i];
        a = __fadd_rn(a, __fmul_rn(v, v));
    }
#pragma unroll
    for (int off = 16; off >= 1; off >>= 1)
        a = __fadd_rn(a, __shfl_down_sync(0xffffffffu, a, off));
    float x2 = __shfl_sync(0xffffffffu, a, 0);

    float c2ab[2];
#pragma unroll
    for (int s = 0; s < 2; s++) {
        const float* cr = c + (size_t)(s ? kb : ka) * Dn;
        float b = 0.f;
#pragma unroll
        for (int i = 0; i < 4; i++) {
            float v = cr[lane + 32 * i];
            b = __fadd_rn(b, __fmul_rn(v, v));
        }
#pragma unroll
        for (int off = 16; off >= 1; off >>= 1)
            b = __fadd_rn(b, __shfl_down_sync(0xffffffffu, b, off));
        c2ab[s] = __shfl_sync(0xffffffffu, b, 0);
    }

    float dd = 0.f;
    if (lane < 2) {
        const float* cr = c + (size_t)(lane ? kb : ka) * Dn;
        for (int d = 0; d < Dn; d++)
            dd = __fmaf_rn(xr[d], cr[d], dd);
    }
    float dota = __shfl_sync(0xffffffffu, dd, 0);
    float dotb = __shfl_sync(0xffffffffu, dd, 1);

    if (lane == 0) {
        float ta = __fsub_rn(__fadd_rn(x2, c2ab[0]), __fmul_rn(2.0f, dota));
        float tb = __fsub_rn(__fadd_rn(x2, c2ab[1]), __fmul_rn(2.0f, dotb));
        float sa = __fsqrt_rn(fmaxf(ta, 0.0f));
        float sb = __fsqrt_rn(fmaxf(tb, 0.0f));
        int win = ka;
        if (sb < sa || (sb == sa && kb < ka)) win = kb;
        g_label[row] = win;
    }
}

// ---------------------------------------------------------------------------
// Fused output: gather + center passthrough + labels (validated R12-R15)
// ---------------------------------------------------------------------------
#define N1 (Bn * D4)
#define N2 (Kn * D4)
#define N3 (Bn / 4)
__global__ void out_all_kernel(const float* __restrict__ c, float* __restrict__ out) {
    int idx = blockIdx.x * blockDim.x + threadIdx.x;
    if (idx < N1) {
        int b = idx >> 5, d4 = idx & 31;
        ((float4*)out)[idx] = ((const float4*)c)[g_label[b] * D4 + d4];
    } else if (idx < N1 + N2) {
        ((float4*)out)[idx] = ((const float4*)c)[idx - N1];
    } else if (idx < N1 + N2 + N3) {
        int i = idx - N1 - N2;
        float4 v = make_float4((float)g_label[4 * i],     (float)g_label[4 * i + 1],
                               (float)g_label[4 * i + 2], (float)g_label[4 * i + 3]);
        ((float4*)out)[idx] = v;
    }
}

__global__ void gather_kernel(const float* __restrict__ c, float* __restrict__ out) {
    int idx = blockIdx.x * blockDim.x + threadIdx.x;
    if (idx >= N1) return;
    int b = idx >> 5, d4 = idx & 31;
    ((float4*)out)[idx] = ((const float4*)c)[g_label[b] * D4 + d4];
}

__global__ void label_out_kernel(float* __restrict__ dst) {
    int b = blockIdx.x * blockDim.x + threadIdx.x;
    if (b >= Bn) return;
    dst[b] = (float)g_label[b];
}

// ---------------------------------------------------------------------------
extern "C" void kernel_launch(void* const* d_in, const int* in_sizes, int n_in,
                              void* d_out, int out_size) {
    const float* x = (const float*)d_in[0];
    const float* c = (const float*)d_in[1];
    if (n_in >= 2 && in_sizes[0] == Kn * Dn && in_sizes[1] == Bn * Dn) {
        const float* t = x; x = c; c = t;
    }
    float* out = (float*)d_out;

    static bool attr_done = false;
    if (!attr_done) {
        cudaFuncSetAttribute(hmma_argmin_kernel,
                             cudaFuncAttributeMaxDynamicSharedMemorySize, SMEM_TOTAL);
        attr_done = true;
    }

    __nv_bfloat16 *xhi, *xlo, *chi, *clo;
    cudaGetSymbolAddress((void**)&xhi, g_xhi);
    cudaGetSymbolAddress((void**)&xlo, g_xlo);
    cudaGetSymbolAddress((void**)&chi, g_chi);
    cudaGetSymbolAddress((void**)&clo, g_clo);

    convert_kernel<<<(Bn * D4 + 255) / 256, 256>>>(x, xhi, xlo, Bn * D4);
    convert_c_kernel<<<(Kn * D4 + 255) / 256, 256>>>(c, chi, clo);
    hmma_argmin_kernel<<<Bn / MTILE, THREADS, SMEM_TOTAL>>>();
    fixup_kernel<<<(Bn * 32 + 255) / 256, 256>>>(x, c);

    if (out_size >= N1 * 4 + N2 * 4 + Bn) {
        out_all_kernel<<<(N1 + N2 + N3 + 255) / 256, 256>>>(c, out);
    } else if (out_size >= Bn * Dn) {
        gather_kernel<<<(N1 + 255) / 256, 256>>>(c, out);
        if (out_size - Bn * Dn >= Bn)
            label_out_kernel<<<(Bn + 255) / 256, 256>>>(out + (size_t)Bn * Dn);
    } else if (out_size >= Bn) {
        label_out_kernel<<<(Bn + 255) / 256, 256>>>(out);
    }
}